// round 16
// baseline (speedup 1.0000x reference)
#include <cuda_runtime.h>

// Problem constants
static constexpr int S  = 512;
static constexpr int B  = 256;
static constexpr int NI = 784;
static constexpr int H  = 10;

static constexpr int ROWS = S * B;          // 131072 GEMM rows
static constexpr int TPB  = 256;            // threads per block (GEMM)
static constexpr int RPB  = 512;            // rows per block (2 per thread)
static constexpr int GRID = ROWS / RPB;     // 256 blocks
static constexpr int NC4  = NI / 4;         // 196 float4 per x row
static constexpr int C4PAD = 200;           // padded (25 chunks of 8 float4)

static constexpr int WT_ROWS  = 800;        // padded i-dimension (zeros beyond 784)
static constexpr int WT_PITCH = 12;         // floats per Wt row (10 + 2 pad, 48B)
static constexpr int XS_PITCH4 = 9;         // float4 per staged x row (36 floats == 4 mod 32 -> conflict-free)
static constexpr int SMEM_WT  = WT_ROWS * WT_PITCH * 4;   // 38400 B
static constexpr int SMEM_XS  = RPB * XS_PITCH4 * 16;     // 73728 B
static constexpr int SMEM_TOTAL = SMEM_WT + SMEM_XS;      // 112128 B -> 2 blocks/SM

// ---- packed f32x2 helpers (FFMA2: 2x fp32 FMA per instruction) ----
__device__ __forceinline__ unsigned long long pfma2(unsigned long long a,
                                                    unsigned long long b,
                                                    unsigned long long c) {
    unsigned long long d;
    asm("fma.rn.f32x2 %0, %1, %2, %3;" : "=l"(d) : "l"(a), "l"(b), "l"(c));
    return d;
}
__device__ __forceinline__ unsigned long long dup2(float x) {
    unsigned long long d;
    unsigned u = __float_as_uint(x);
    asm("mov.b64 %0, {%1, %2};" : "=l"(d) : "r"(u), "r"(u));
    return d;
}
__device__ __forceinline__ void unpack2(unsigned long long a, float& lo, float& hi) {
    unsigned l, h;
    asm("mov.b64 {%0, %1}, %2;" : "=r"(l), "=r"(h) : "l"(a));
    lo = __uint_as_float(l);
    hi = __uint_as_float(h);
}

// ============================================================================
// Kernel 1: xi[s,b,:] = x[s,b,:] @ W_ih^T + (b_ih + b_hh), written into d_out.
// Each thread owns 2 rows; W^T broadcast from shared; x staged through shared
// for coalesced global loads; packed f32x2 FMAs.
// ============================================================================
__global__ void __launch_bounds__(TPB, 2) xproj_kernel(
    const float* __restrict__ x,
    const float* __restrict__ W_ih,
    const float* __restrict__ b_ih,
    const float* __restrict__ b_hh,
    float* __restrict__ out)
{
    extern __shared__ char smem[];
    float*  Wt  = reinterpret_cast<float*>(smem);               // [800][12]
    float4* xs4 = reinterpret_cast<float4*>(smem + SMEM_WT);    // [512][9]

    const int t = threadIdx.x;
    const int rows_base = blockIdx.x * RPB;

    // Fill Wt (transposed W_ih, padded with zeros)
    for (int idx = t; idx < WT_ROWS * WT_PITCH; idx += TPB) {
        int i = idx / WT_PITCH;
        int j = idx - i * WT_PITCH;
        Wt[idx] = (j < H && i < NI) ? W_ih[j * NI + i] : 0.0f;
    }

    unsigned long long acc0[5], acc1[5];
#pragma unroll
    for (int j5 = 0; j5 < 5; ++j5) { acc0[j5] = 0ull; acc1[j5] = 0ull; }

    const float4* x4 = reinterpret_cast<const float4*>(x);

    for (int c4 = 0; c4 < C4PAD; c4 += 8) {
        __syncthreads();
        // Stage 512 rows x 8 float4 of x (coalesced: consecutive threads ->
        // consecutive 16B within a row, 8 threads per row-chunk)
#pragma unroll
        for (int k = 0; k < 16; ++k) {
            int flat = k * TPB + t;           // 0..4095
            int lr = flat >> 3;
            int q  = flat & 7;
            int g  = c4 + q;
            float4 v = make_float4(0.0f, 0.0f, 0.0f, 0.0f);
            if (g < NC4) v = x4[(long)(rows_base + lr) * NC4 + g];
            xs4[lr * XS_PITCH4 + q] = v;
        }
        __syncthreads();

#pragma unroll
        for (int q = 0; q < 8; ++q) {
            float4 a0 = xs4[t * XS_PITCH4 + q];
            float4 a1 = xs4[(t + TPB) * XS_PITCH4 + q];
            float xv0[4] = {a0.x, a0.y, a0.z, a0.w};
            float xv1[4] = {a1.x, a1.y, a1.z, a1.w};
#pragma unroll
            for (int p = 0; p < 4; ++p) {
                int i = (c4 + q) * 4 + p;
                const ulonglong2* wr =
                    reinterpret_cast<const ulonglong2*>(Wt + i * WT_PITCH);
                ulonglong2 wa = wr[0];   // (w0,w1),(w2,w3)
                ulonglong2 wb = wr[1];   // (w4,w5),(w6,w7)
                ulonglong2 wc = wr[2];   // (w8,w9),(pad)
                unsigned long long d0 = dup2(xv0[p]);
                unsigned long long d1 = dup2(xv1[p]);
                acc0[0] = pfma2(d0, wa.x, acc0[0]);
                acc0[1] = pfma2(d0, wa.y, acc0[1]);
                acc0[2] = pfma2(d0, wb.x, acc0[2]);
                acc0[3] = pfma2(d0, wb.y, acc0[3]);
                acc0[4] = pfma2(d0, wc.x, acc0[4]);
                acc1[0] = pfma2(d1, wa.x, acc1[0]);
                acc1[1] = pfma2(d1, wa.y, acc1[1]);
                acc1[2] = pfma2(d1, wb.x, acc1[2]);
                acc1[3] = pfma2(d1, wb.y, acc1[3]);
                acc1[4] = pfma2(d1, wc.x, acc1[4]);
            }
        }
    }

    // Stage results (+bias) in shared, then coalesced float4 store to global.
    __syncthreads();
    float* ost = reinterpret_cast<float*>(xs4);   // reuse: [512][10]
#pragma unroll
    for (int j5 = 0; j5 < 5; ++j5) {
        float bl = __ldg(&b_ih[2 * j5])     + __ldg(&b_hh[2 * j5]);
        float bh = __ldg(&b_ih[2 * j5 + 1]) + __ldg(&b_hh[2 * j5 + 1]);
        float l0, h0, l1, h1;
        unpack2(acc0[j5], l0, h0);
        unpack2(acc1[j5], l1, h1);
        ost[t * H + 2 * j5]             = l0 + bl;
        ost[t * H + 2 * j5 + 1]         = h0 + bh;
        ost[(t + TPB) * H + 2 * j5]     = l1 + bl;
        ost[(t + TPB) * H + 2 * j5 + 1] = h1 + bh;
    }
    __syncthreads();
    float4* og = reinterpret_cast<float4*>(out + (long)rows_base * H);
    const float4* os4 = reinterpret_cast<const float4*>(ost);
#pragma unroll
    for (int k = 0; k < 5; ++k) og[k * TPB + t] = os4[k * TPB + t];
}

// ============================================================================
// Kernel 2: sequential recurrence h_t = relu(xi_t + h_{t-1} @ W_hh^T),
// in-place over d_out; appends h_last at offset S*B*H.
// 3 batch rows per warp (lane = u*10 + j), h exchanged via SHFL, xi
// prefetched 4 steps ahead (L2-resident).
// ============================================================================
static constexpr int BPW    = 3;
static constexpr int NWARPS = (B + BPW - 1) / BPW;   // 86

__global__ void scan_kernel(const float* __restrict__ W_hh, float* out)
{
    const int lane = threadIdx.x;
    const int u = lane / H;                 // 0..3 (3 only for lanes 30,31)
    const int j = lane - u * H;             // 0..9
    const int b = blockIdx.x * BPW + u;
    const bool active = (u < BPW) && (b < B);
    const int srcbase = (u < BPW ? u : 0) * H;

    float w[10];
#pragma unroll
    for (int k = 0; k < 10; ++k) w[k] = __ldg(&W_hh[j * H + k]);

    const int stride = B * H;               // 2560
    const int idx0 = b * H + j;             // stays in-bounds even for idle lanes

    float h = 0.0f;
    float xibuf[4];
#pragma unroll
    for (int tt = 0; tt < 4; ++tt) xibuf[tt] = out[tt * stride + idx0];

#pragma unroll 4
    for (int tt = 0; tt < S; ++tt) {
        float acc = xibuf[tt & 3];
        if (tt + 4 < S) xibuf[tt & 3] = out[(tt + 4) * stride + idx0];
#pragma unroll
        for (int k = 0; k < 10; ++k) {
            float hk = __shfl_sync(0xffffffffu, h, srcbase + k);
            acc = fmaf(hk, w[k], acc);
        }
        h = fmaxf(acc, 0.0f);
        if (active) out[tt * stride + idx0] = h;
    }
    // h_n tail: [1, B, H] right after out[S,B,H]
    if (active) out[S * stride + idx0] = h;
}

extern "C" void kernel_launch(void* const* d_in, const int* in_sizes, int n_in,
                              void* d_out, int out_size) {
    const float* x    = (const float*)d_in[0];
    const float* W_ih = (const float*)d_in[1];
    const float* W_hh = (const float*)d_in[2];
    const float* b_ih = (const float*)d_in[3];
    const float* b_hh = (const float*)d_in[4];
    float* out = (float*)d_out;

    cudaFuncSetAttribute(xproj_kernel,
                         cudaFuncAttributeMaxDynamicSharedMemorySize,
                         SMEM_TOTAL);

    xproj_kernel<<<GRID, TPB, SMEM_TOTAL>>>(x, W_ih, b_ih, b_hh, out);
    scan_kernel<<<NWARPS, 32>>>(W_hh, out);
}